// round 7
// baseline (speedup 1.0000x reference)
#include <cuda_runtime.h>
#include <cuda_fp16.h>
#include <cstdint>

// ---------------- problem constants ----------------
#define VOCAB 32000
#define EMB   64
#define BATCH 4
#define SEQ   2048
#define MROWS (BATCH * SEQ)   // 8192

// GEMM tiling
#define BM 128
#define BN 128
#define HPITCH 72                        // halves; conflict-free fragment LDS
#define TILE_BYTES (128 * HPITCH * 2)    // 18432

// smem: B tile + double-buffered A tiles + epilogue staging
#define SOFF_B   0
#define SOFF_A0  TILE_BYTES
#define SOFF_A1  (2 * TILE_BYTES)
#define SOFF_STG (3 * TILE_BYTES)        // 8 warps x 16x36 fp32 = 18432
#define SMEM_SZ  (4 * TILE_BYTES)        // 73728 -> 2 CTAs/SM

// device scratch
__device__ __half g_A[MROWS * EMB];      // prefix means, fp16
__device__ __half g_Wh[VOCAB * EMB];     // W, fp16

// ---------------- helpers ----------------
__device__ __forceinline__ uint32_t smem_u32(const void* p) {
    uint32_t a;
    asm("{ .reg .u64 t; cvta.to.shared.u64 t, %1; cvt.u32.u64 %0, t; }" : "=r"(a) : "l"(p));
    return a;
}
__device__ __forceinline__ void mma_f16(float c[4],
                                        uint32_t a0, uint32_t a1, uint32_t a2, uint32_t a3,
                                        uint32_t b0, uint32_t b1) {
    asm volatile(
        "mma.sync.aligned.m16n8k16.row.col.f32.f16.f16.f32 "
        "{%0,%1,%2,%3}, {%4,%5,%6,%7}, {%8,%9}, {%0,%1,%2,%3};"
        : "+f"(c[0]), "+f"(c[1]), "+f"(c[2]), "+f"(c[3])
        : "r"(a0), "r"(a1), "r"(a2), "r"(a3), "r"(b0), "r"(b1));
}
#define CP_ASYNC16(saddr, gptr) \
    asm volatile("cp.async.cg.shared.global [%0], [%1], 16;" :: "r"(saddr), "l"(gptr))
#define CP_COMMIT() asm volatile("cp.async.commit_group;" ::: "memory")
#define CP_WAIT(n)  asm volatile("cp.async.wait_group %0;" :: "n"(n) : "memory")

// ---------------- fused prep kernel ----------------
// blocks [0,128): per-(batch,chunk) gather + redundant lookback + scan -> g_A fp16
// blocks [128,628): W -> fp16 conversion
__global__ void __launch_bounds__(512) prep_kernel(const float* __restrict__ emb,
                                                   const float* __restrict__ W,
                                                   const int* __restrict__ x) {
    const int bid = blockIdx.x;
    const int t = threadIdx.x;

    if (bid >= 128) {
        // ---- W conversion: 4096 floats per block ----
        const int i = (bid - 128) * 512 + t;   // 8-float chunk index
        const float4* src = reinterpret_cast<const float4*>(W) + (size_t)i * 2;
        float4 v0 = src[0];
        float4 v1 = src[1];
        __half2 h[4];
        h[0] = __floats2half2_rn(v0.x, v0.y);
        h[1] = __floats2half2_rn(v0.z, v0.w);
        h[2] = __floats2half2_rn(v1.x, v1.y);
        h[3] = __floats2half2_rn(v1.z, v1.w);
        *reinterpret_cast<uint4*>(g_Wh + (size_t)i * 8) = *reinterpret_cast<uint4*>(h);
        return;
    }

    // ---- chunk block: batch b, chunk c (64 positions) ----
    __shared__ float ebuf[64 * 64];   // gathered chunk embeddings -> in-place scan
    __shared__ float part[8 * 64];    // lookback partials
    __shared__ float off[64];         // summed offset per feature

    const int b = bid >> 5;
    const int c = bid & 31;
    const int p0 = c * 64;

    // gather this chunk's 64 embedding rows
    const int i = t >> 3;   // position in chunk 0..63
    const int q = t & 7;    // feature octet
    {
        const int idx = x[b * SEQ + p0 + i];
        const float4* src = reinterpret_cast<const float4*>(emb + (size_t)idx * EMB) + q * 2;
        float4 v0 = src[0];
        float4 v1 = src[1];
        *reinterpret_cast<float4*>(ebuf + i * 64 + q * 8)     = v0;
        *reinterpret_cast<float4*>(ebuf + i * 64 + q * 8 + 4) = v1;
    }

    // redundant lookback: sum embeddings of ALL previous positions.
    // 8 position-groups x 64 features; coalesced 256B row reads per group.
    {
        const int g = t >> 6;    // 0..7
        const int e = t & 63;    // feature
        float partial = 0.0f;
        const int* xb = x + b * SEQ;
        #pragma unroll 4
        for (int p = g; p < p0; p += 8) {
            const int id2 = xb[p];
            partial += emb[(size_t)id2 * EMB + e];
        }
        part[(t >> 6) * 64 + e] = partial;
    }
    __syncthreads();

    // reduce lookback partials + chunk-local inclusive scan (in-place)
    if (t < 64) {
        float o = 0.0f;
        #pragma unroll
        for (int gg = 0; gg < 8; ++gg) o += part[gg * 64 + t];
        off[t] = o;
        float run = 0.0f;
        #pragma unroll 8
        for (int p = 0; p < 64; ++p) {
            run += ebuf[p * 64 + t];
            ebuf[p * 64 + t] = run;
        }
    }
    __syncthreads();

    // apply offset, scale by 1/(pos+1), round to fp16, write g_A
    {
        const float inv = __fdividef(1.0f, (float)(p0 + i + 1));
        const float* sb = ebuf + i * 64 + q * 8;
        const float* ob = off + q * 8;
        __half2 h[4];
        h[0] = __floats2half2_rn((sb[0] + ob[0]) * inv, (sb[1] + ob[1]) * inv);
        h[1] = __floats2half2_rn((sb[2] + ob[2]) * inv, (sb[3] + ob[3]) * inv);
        h[2] = __floats2half2_rn((sb[4] + ob[4]) * inv, (sb[5] + ob[5]) * inv);
        h[3] = __floats2half2_rn((sb[6] + ob[6]) * inv, (sb[7] + ob[7]) * inv);
        *reinterpret_cast<uint4*>(g_A + (size_t)(b * SEQ + p0 + i) * EMB + q * 8) =
            *reinterpret_cast<uint4*>(h);
    }
}

// ---------------- GEMM: fp16 mma.sync, double-buffered A, coalesced staged epilogue ----
// (unchanged from round 6 — proven 243.7us config)
__global__ void __launch_bounds__(256, 2) gemm_kernel(const float* __restrict__ bias,
                                                      float* __restrict__ out) {
    extern __shared__ char smem[];
    __half* Bs    = reinterpret_cast<__half*>(smem + SOFF_B);
    __half* Abuf0 = reinterpret_cast<__half*>(smem + SOFF_A0);
    __half* Abuf1 = reinterpret_cast<__half*>(smem + SOFF_A1);

    const int tid  = threadIdx.x;
    const int wid  = tid >> 5;
    const int lane = tid & 31;
    const int gid  = lane >> 2;   // 0..7
    const int tig  = lane & 3;    // 0..3
    const int mw   = wid >> 2;    // warp M index 0..1
    const int nw   = wid & 3;     // warp N index 0..3
    const int n0   = blockIdx.x * BN;
    const int yb   = blockIdx.y;  // 0..7

    const uint32_t sB  = smem_u32(Bs);
    const uint32_t sA0 = smem_u32(Abuf0);
    const uint32_t sA1 = smem_u32(Abuf1);

    float* stg = reinterpret_cast<float*>(smem + SOFF_STG) + wid * (16 * 36);
    const int sr = lane >> 3;   // 0..3
    const int sc = lane & 7;    // 0..7

    float bias_r[4][2];
    #pragma unroll
    for (int nt = 0; nt < 4; ++nt) {
        float2 bv = *reinterpret_cast<const float2*>(bias + n0 + nw * 32 + nt * 8 + 2 * tig);
        bias_r[nt][0] = bv.x;
        bias_r[nt][1] = bv.y;
    }

    {
        const __half* gB = g_Wh + (size_t)n0 * EMB;
        #pragma unroll
        for (int it = 0; it < 4; ++it) {
            const int lin = it * 256 + tid;
            const int r = lin >> 3, f8 = lin & 7;
            CP_ASYNC16(sB + (uint32_t)(r * HPITCH + f8 * 8) * 2, gB + r * EMB + f8 * 8);
        }
        const __half* gA = g_A + (size_t)(yb * BM) * EMB;
        #pragma unroll
        for (int it = 0; it < 4; ++it) {
            const int lin = it * 256 + tid;
            const int r = lin >> 3, f8 = lin & 7;
            CP_ASYNC16(sA0 + (uint32_t)(r * HPITCH + f8 * 8) * 2, gA + r * EMB + f8 * 8);
        }
        CP_COMMIT();
    }

    #pragma unroll 1
    for (int j = 0; j < 8; ++j) {
        if (j < 7) {
            const uint32_t sdst = (j & 1) ? sA0 : sA1;
            const __half* gA = g_A + (size_t)((yb + (j + 1) * 8) * BM) * EMB;
            #pragma unroll
            for (int it = 0; it < 4; ++it) {
                const int lin = it * 256 + tid;
                const int r = lin >> 3, f8 = lin & 7;
                CP_ASYNC16(sdst + (uint32_t)(r * HPITCH + f8 * 8) * 2, gA + r * EMB + f8 * 8);
            }
            CP_COMMIT();
            CP_WAIT(1);
        } else {
            CP_WAIT(0);
        }
        __syncthreads();

        const __half* Ac = (j & 1) ? Abuf1 : Abuf0;

        float acc[4][4][4];
        #pragma unroll
        for (int mt = 0; mt < 4; ++mt)
            #pragma unroll
            for (int nt = 0; nt < 4; ++nt)
                #pragma unroll
                for (int rr = 0; rr < 4; ++rr) acc[mt][nt][rr] = 0.0f;

        #pragma unroll
        for (int ks = 0; ks < 4; ++ks) {
            const int k0 = ks * 16;
            uint32_t a[4][4];
            #pragma unroll
            for (int mt = 0; mt < 4; ++mt) {
                const __half* ap = Ac + (mw * 64 + mt * 16 + gid) * HPITCH + k0 + 2 * tig;
                a[mt][0] = *reinterpret_cast<const uint32_t*>(ap);
                a[mt][1] = *reinterpret_cast<const uint32_t*>(ap + 8 * HPITCH);
                a[mt][2] = *reinterpret_cast<const uint32_t*>(ap + 8);
                a[mt][3] = *reinterpret_cast<const uint32_t*>(ap + 8 * HPITCH + 8);
            }
            uint32_t bb[4][2];
            #pragma unroll
            for (int nt = 0; nt < 4; ++nt) {
                const __half* bp = Bs + (nw * 32 + nt * 8 + gid) * HPITCH + k0 + 2 * tig;
                bb[nt][0] = *reinterpret_cast<const uint32_t*>(bp);
                bb[nt][1] = *reinterpret_cast<const uint32_t*>(bp + 8);
            }
            #pragma unroll
            for (int mt = 0; mt < 4; ++mt)
                #pragma unroll
                for (int nt = 0; nt < 4; ++nt)
                    mma_f16(acc[mt][nt], a[mt][0], a[mt][1], a[mt][2], a[mt][3],
                            bb[nt][0], bb[nt][1]);
        }

        __syncthreads();

        const int m0 = (yb + j * 8) * BM;
        #pragma unroll
        for (int mt = 0; mt < 4; ++mt) {
            #pragma unroll
            for (int nt = 0; nt < 4; ++nt) {
                const int cc = nt * 8 + 2 * tig;
                float2 v0 = make_float2(acc[mt][nt][0] + bias_r[nt][0],
                                        acc[mt][nt][1] + bias_r[nt][1]);
                float2 v1 = make_float2(acc[mt][nt][2] + bias_r[nt][0],
                                        acc[mt][nt][3] + bias_r[nt][1]);
                *reinterpret_cast<float2*>(stg + gid * 36 + cc) = v0;
                *reinterpret_cast<float2*>(stg + (gid + 8) * 36 + cc) = v1;
            }
            __syncwarp();
            const int row_base = m0 + mw * 64 + mt * 16;
            #pragma unroll
            for (int rr = 0; rr < 4; ++rr) {
                const int r = rr * 4 + sr;
                float4 v = *reinterpret_cast<const float4*>(stg + r * 36 + sc * 4);
                *reinterpret_cast<float4*>(out + (size_t)(row_base + r) * VOCAB +
                                           n0 + nw * 32 + sc * 4) = v;
            }
            __syncwarp();
        }
    }
}

// ---------------- launch ----------------
extern "C" void kernel_launch(void* const* d_in, const int* in_sizes, int n_in,
                              void* d_out, int out_size) {
    const float* emb  = (const float*)d_in[0];   // [32000, 64] f32
    const float* Wm   = (const float*)d_in[1];   // [32000, 64] f32
    const float* bias = (const float*)d_in[2];   // [32000] f32
    const int*   x    = (const int*)d_in[3];     // [4, 2048] i32
    float* out = (float*)d_out;                  // [4, 2048, 32000] f32

    // 128 chunk blocks + 500 W-convert blocks
    prep_kernel<<<628, 512>>>(emb, Wm, x);

    cudaFuncSetAttribute(gemm_kernel, cudaFuncAttributeMaxDynamicSharedMemorySize, SMEM_SZ);
    dim3 grid(VOCAB / BN, 8);   // (250, 8)
    gemm_kernel<<<grid, 256, SMEM_SZ>>>(bias, out);
}

// round 8
// speedup vs baseline: 1.2236x; 1.2236x over previous
#include <cuda_runtime.h>
#include <cuda_fp16.h>
#include <cstdint>

// ---------------- problem constants ----------------
#define VOCAB 32000
#define EMB   64
#define BATCH 4
#define SEQ   2048
#define MROWS (BATCH * SEQ)   // 8192

// GEMM tiling
#define BM 128
#define BN 128
#define HPITCH 72                        // halves; conflict-free fragment LDS
#define TILE_BYTES (128 * HPITCH * 2)    // 18432

// smem: B tile + double-buffered A tiles (no epilogue staging needed)
#define SOFF_B   0
#define SOFF_A0  TILE_BYTES
#define SOFF_A1  (2 * TILE_BYTES)
#define SMEM_SZ  (3 * TILE_BYTES)        // 55296 -> 2 CTAs/SM

// device scratch
__device__ __half g_A[MROWS * EMB];       // prefix means, fp16
__device__ __half g_Wh[VOCAB * EMB];      // W, fp16
__device__ float  g_S[MROWS * EMB];       // fp32 chunk-local prefix sums
__device__ float  g_csum[BATCH * 32 * EMB];
__device__ float  g_coff[BATCH * 32 * EMB];

// ---------------- helpers ----------------
__device__ __forceinline__ uint32_t smem_u32(const void* p) {
    uint32_t a;
    asm("{ .reg .u64 t; cvta.to.shared.u64 t, %1; cvt.u32.u64 %0, t; }" : "=r"(a) : "l"(p));
    return a;
}
__device__ __forceinline__ void mma_f16(float c[4],
                                        uint32_t a0, uint32_t a1, uint32_t a2, uint32_t a3,
                                        uint32_t b0, uint32_t b1) {
    asm volatile(
        "mma.sync.aligned.m16n8k16.row.col.f32.f16.f16.f32 "
        "{%0,%1,%2,%3}, {%4,%5,%6,%7}, {%8,%9}, {%0,%1,%2,%3};"
        : "+f"(c[0]), "+f"(c[1]), "+f"(c[2]), "+f"(c[3])
        : "r"(a0), "r"(a1), "r"(a2), "r"(a3), "r"(b0), "r"(b1));
}
#define CP_ASYNC16(saddr, gptr) \
    asm volatile("cp.async.cg.shared.global [%0], [%1], 16;" :: "r"(saddr), "l"(gptr))
#define CP_COMMIT() asm volatile("cp.async.commit_group;" ::: "memory")
#define CP_WAIT(n)  asm volatile("cp.async.wait_group %0;" :: "n"(n) : "memory")

// column permutation within each 16-row group of the B tile:
// q<8 -> 4*(q>>1)+(q&1) ; q>=8 -> 4*((q&7)>>1)+(q&1)+2
__device__ __forceinline__ int bperm(int q) {
    const int q7 = q & 7;
    return ((q7 >> 1) << 2) + (q & 1) + ((q & 8) ? 2 : 0);
}

// ---------------- kernel 0: W -> fp16 copy ----------------
__global__ void __launch_bounds__(256) wprep_kernel(const float* __restrict__ W) {
    const int i = blockIdx.x * 256 + threadIdx.x;  // 8 floats per thread
    const float4* src = reinterpret_cast<const float4*>(W) + i * 2;
    float4 v0 = src[0];
    float4 v1 = src[1];
    __half2 h[4];
    h[0] = __floats2half2_rn(v0.x, v0.y);
    h[1] = __floats2half2_rn(v0.z, v0.w);
    h[2] = __floats2half2_rn(v1.x, v1.y);
    h[3] = __floats2half2_rn(v1.z, v1.w);
    *reinterpret_cast<uint4*>(g_Wh + (size_t)i * 8) = *reinterpret_cast<uint4*>(h);
}

// ---------------- prefix phase 1: chunk-local gather + scan (unscaled fp32) ----------------
__global__ void __launch_bounds__(512) p1_kernel(const float* __restrict__ emb,
                                                 const int* __restrict__ x) {
    __shared__ float ebuf[64 * 64];
    const int c = blockIdx.x, b = blockIdx.y;
    const int t = threadIdx.x;
    const int i = t >> 3, q = t & 7;
    const int p0 = c * 64;
    const int idx = x[b * SEQ + p0 + i];
    const float4* src = reinterpret_cast<const float4*>(emb + (size_t)idx * EMB) + q * 2;
    float4 v0 = src[0];
    float4 v1 = src[1];
    *reinterpret_cast<float4*>(ebuf + i * 64 + q * 8)     = v0;
    *reinterpret_cast<float4*>(ebuf + i * 64 + q * 8 + 4) = v1;
    __syncthreads();
    if (t < 64) {
        float run = 0.0f;
        #pragma unroll 8
        for (int p = 0; p < 64; ++p) {
            run += ebuf[p * 64 + t];
            g_S[(size_t)(b * SEQ + p0 + p) * EMB + t] = run;
        }
        g_csum[(b * 32 + c) * EMB + t] = run;
    }
}

// ---------------- prefix phase 2: per-batch exclusive scan of chunk sums ----------------
__global__ void __launch_bounds__(64) p2_kernel() {
    const int b = blockIdx.x, e = threadIdx.x;
    float off = 0.0f;
    #pragma unroll
    for (int c = 0; c < 32; ++c) {
        g_coff[(b * 32 + c) * EMB + e] = off;
        off += g_csum[(b * 32 + c) * EMB + e];
    }
}

// ---------------- prefix phase 3: apply offsets, scale, fp16-round ----------------
__global__ void __launch_bounds__(512) p3_kernel() {
    const int c = blockIdx.x, b = blockIdx.y;
    const int t = threadIdx.x;
    const int i = t >> 3, q = t & 7;
    const int p = c * 64 + i;
    const float inv = __fdividef(1.0f, (float)(p + 1));
    const float* base  = g_S + (size_t)(b * SEQ + p) * EMB + q * 8;
    const float* obase = g_coff + (size_t)(b * 32 + c) * EMB + q * 8;
    float4 a0 = *reinterpret_cast<const float4*>(base);
    float4 a1 = *reinterpret_cast<const float4*>(base + 4);
    float4 o0 = *reinterpret_cast<const float4*>(obase);
    float4 o1 = *reinterpret_cast<const float4*>(obase + 4);
    __half2 h[4];
    h[0] = __floats2half2_rn((a0.x + o0.x) * inv, (a0.y + o0.y) * inv);
    h[1] = __floats2half2_rn((a0.z + o0.z) * inv, (a0.w + o0.w) * inv);
    h[2] = __floats2half2_rn((a1.x + o1.x) * inv, (a1.y + o1.y) * inv);
    h[3] = __floats2half2_rn((a1.z + o1.z) * inv, (a1.w + o1.w) * inv);
    *reinterpret_cast<uint4*>(g_A + (size_t)(b * SEQ + p) * EMB + q * 8) =
        *reinterpret_cast<uint4*>(h);
}

// ---------------- GEMM: fp16 mma.sync, permuted-B direct float4 epilogue ----------------
// out[m, n] = sum_k A[m,k] * W[n,k] + bias[n]
__global__ void __launch_bounds__(256, 2) gemm_kernel(const float* __restrict__ bias,
                                                      float* __restrict__ out) {
    extern __shared__ char smem[];
    __half* Bs    = reinterpret_cast<__half*>(smem + SOFF_B);
    __half* Abuf0 = reinterpret_cast<__half*>(smem + SOFF_A0);
    __half* Abuf1 = reinterpret_cast<__half*>(smem + SOFF_A1);

    const int tid  = threadIdx.x;
    const int wid  = tid >> 5;
    const int lane = tid & 31;
    const int gid  = lane >> 2;   // 0..7
    const int tig  = lane & 3;    // 0..3
    const int mw   = wid >> 2;    // warp M index 0..1
    const int nw   = wid & 3;     // warp N index 0..3
    const int n0   = blockIdx.x * BN;
    const int yb   = blockIdx.y;  // 0..7

    const uint32_t sB  = smem_u32(Bs);
    const uint32_t sA0 = smem_u32(Abuf0);
    const uint32_t sA1 = smem_u32(Abuf1);

    // bias -> registers: one float4 per 16-col pair (cols are contiguous post-perm)
    float4 bias_r[2];
    #pragma unroll
    for (int p = 0; p < 2; ++p)
        bias_r[p] = *reinterpret_cast<const float4*>(bias + n0 + nw * 32 + p * 16 + 4 * tig);

    // issue B tile (column-PERMUTED rows) + A tile j=0
    {
        const __half* gB = g_Wh + (size_t)n0 * EMB;
        #pragma unroll
        for (int it = 0; it < 4; ++it) {
            const int lin = it * 256 + tid;
            const int r = lin >> 3, f8 = lin & 7;      // r: smem slot row 0..127
            const int wr = (r & ~15) + bperm(r & 15);  // source W row (within tile)
            CP_ASYNC16(sB + (uint32_t)(r * HPITCH + f8 * 8) * 2, gB + wr * EMB + f8 * 8);
        }
        const __half* gA = g_A + (size_t)(yb * BM) * EMB;
        #pragma unroll
        for (int it = 0; it < 4; ++it) {
            const int lin = it * 256 + tid;
            const int r = lin >> 3, f8 = lin & 7;
            CP_ASYNC16(sA0 + (uint32_t)(r * HPITCH + f8 * 8) * 2, gA + r * EMB + f8 * 8);
        }
        CP_COMMIT();
    }

    #pragma unroll 1
    for (int j = 0; j < 8; ++j) {
        if (j < 7) {
            const uint32_t sdst = (j & 1) ? sA0 : sA1;
            const __half* gA = g_A + (size_t)((yb + (j + 1) * 8) * BM) * EMB;
            #pragma unroll
            for (int it = 0; it < 4; ++it) {
                const int lin = it * 256 + tid;
                const int r = lin >> 3, f8 = lin & 7;
                CP_ASYNC16(sdst + (uint32_t)(r * HPITCH + f8 * 8) * 2, gA + r * EMB + f8 * 8);
            }
            CP_COMMIT();
            CP_WAIT(1);
        } else {
            CP_WAIT(0);
        }
        __syncthreads();

        const __half* Ac = (j & 1) ? Abuf1 : Abuf0;

        // ---- mainloop: 4 k-steps of 16, warp tile 64x32 ----
        float acc[4][4][4];
        #pragma unroll
        for (int mt = 0; mt < 4; ++mt)
            #pragma unroll
            for (int nt = 0; nt < 4; ++nt)
                #pragma unroll
                for (int rr = 0; rr < 4; ++rr) acc[mt][nt][rr] = 0.0f;

        #pragma unroll
        for (int ks = 0; ks < 4; ++ks) {
            const int k0 = ks * 16;
            uint32_t a[4][4];
            #pragma unroll
            for (int mt = 0; mt < 4; ++mt) {
                const __half* ap = Ac + (mw * 64 + mt * 16 + gid) * HPITCH + k0 + 2 * tig;
                a[mt][0] = *reinterpret_cast<const uint32_t*>(ap);
                a[mt][1] = *reinterpret_cast<const uint32_t*>(ap + 8 * HPITCH);
                a[mt][2] = *reinterpret_cast<const uint32_t*>(ap + 8);
                a[mt][3] = *reinterpret_cast<const uint32_t*>(ap + 8 * HPITCH + 8);
            }
            uint32_t bb[4][2];
            #pragma unroll
            for (int nt = 0; nt < 4; ++nt) {
                const __half* bp = Bs + (nw * 32 + nt * 8 + gid) * HPITCH + k0 + 2 * tig;
                bb[nt][0] = *reinterpret_cast<const uint32_t*>(bp);
                bb[nt][1] = *reinterpret_cast<const uint32_t*>(bp + 8);
            }
            #pragma unroll
            for (int mt = 0; mt < 4; ++mt)
                #pragma unroll
                for (int nt = 0; nt < 4; ++nt)
                    mma_f16(acc[mt][nt], a[mt][0], a[mt][1], a[mt][2], a[mt][3],
                            bb[nt][0], bb[nt][1]);
        }

        __syncthreads();   // all reads of A[j] done before next prefetch overwrites

        // ---- epilogue: direct float4 STG (columns contiguous thanks to B perm) ----
        const int m0 = (yb + j * 8) * BM;
        #pragma unroll
        for (int mt = 0; mt < 4; ++mt) {
            const int row0 = m0 + mw * 64 + mt * 16 + gid;
            float* orow = out + (size_t)row0 * VOCAB + n0 + nw * 32 + 4 * tig;
            #pragma unroll
            for (int p = 0; p < 2; ++p) {
                const float4 bv = bias_r[p];
                float4 v0, v1;
                v0.x = acc[mt][2 * p][0] + bv.x;
                v0.y = acc[mt][2 * p][1] + bv.y;
                v0.z = acc[mt][2 * p + 1][0] + bv.z;
                v0.w = acc[mt][2 * p + 1][1] + bv.w;
                v1.x = acc[mt][2 * p][2] + bv.x;
                v1.y = acc[mt][2 * p][3] + bv.y;
                v1.z = acc[mt][2 * p + 1][2] + bv.z;
                v1.w = acc[mt][2 * p + 1][3] + bv.w;
                *reinterpret_cast<float4*>(orow + p * 16) = v0;
                *reinterpret_cast<float4*>(orow + (size_t)8 * VOCAB + p * 16) = v1;
            }
        }
    }
}

// ---------------- launch ----------------
extern "C" void kernel_launch(void* const* d_in, const int* in_sizes, int n_in,
                              void* d_out, int out_size) {
    const float* emb  = (const float*)d_in[0];   // [32000, 64] f32
    const float* Wm   = (const float*)d_in[1];   // [32000, 64] f32
    const float* bias = (const float*)d_in[2];   // [32000] f32
    const int*   x    = (const int*)d_in[3];     // [4, 2048] i32
    float* out = (float*)d_out;                  // [4, 2048, 32000] f32

    wprep_kernel<<<(VOCAB * EMB / 8) / 256, 256>>>(Wm);   // 1000 blocks
    p1_kernel<<<dim3(32, BATCH), 512>>>(emb, x);
    p2_kernel<<<BATCH, 64>>>();
    p3_kernel<<<dim3(32, BATCH), 512>>>();

    cudaFuncSetAttribute(gemm_kernel, cudaFuncAttributeMaxDynamicSharedMemorySize, SMEM_SZ);
    dim3 grid(VOCAB / BN, 8);   // (250, 8)
    gemm_kernel<<<grid, 256, SMEM_SZ>>>(bias, out);
}

// round 9
// speedup vs baseline: 1.2518x; 1.0230x over previous
#include <cuda_runtime.h>
#include <cuda_fp16.h>
#include <cstdint>

// ---------------- problem constants ----------------
#define VOCAB 32000
#define EMB   64
#define BATCH 4
#define SEQ   2048
#define MROWS (BATCH * SEQ)   // 8192

// GEMM tiling
#define BM 128
#define BN 128
#define HPITCH 72                        // halves; conflict-free fragment LDS
#define TILE_BYTES (128 * HPITCH * 2)    // 18432

// smem: B tile + triple-buffered A tiles
#define SOFF_B   0
#define SOFF_A0  TILE_BYTES
#define SOFF_A1  (2 * TILE_BYTES)
#define SOFF_A2  (3 * TILE_BYTES)
#define SMEM_SZ  (4 * TILE_BYTES)        // 73728 -> 2 CTAs/SM

// device scratch
__device__ __half g_A[MROWS * EMB];       // prefix means, fp16
__device__ float  g_S[MROWS * EMB];       // fp32 chunk-local prefix sums
__device__ float  g_csum[BATCH * 32 * EMB];

// ---------------- helpers ----------------
__device__ __forceinline__ uint32_t smem_u32(const void* p) {
    uint32_t a;
    asm("{ .reg .u64 t; cvta.to.shared.u64 t, %1; cvt.u32.u64 %0, t; }" : "=r"(a) : "l"(p));
    return a;
}
__device__ __forceinline__ void mma_f16(float c[4],
                                        uint32_t a0, uint32_t a1, uint32_t a2, uint32_t a3,
                                        uint32_t b0, uint32_t b1) {
    asm volatile(
        "mma.sync.aligned.m16n8k16.row.col.f32.f16.f16.f32 "
        "{%0,%1,%2,%3}, {%4,%5,%6,%7}, {%8,%9}, {%0,%1,%2,%3};"
        : "+f"(c[0]), "+f"(c[1]), "+f"(c[2]), "+f"(c[3])
        : "r"(a0), "r"(a1), "r"(a2), "r"(a3), "r"(b0), "r"(b1));
}
#define CP_ASYNC16(saddr, gptr) \
    asm volatile("cp.async.cg.shared.global [%0], [%1], 16;" :: "r"(saddr), "l"(gptr))
#define CP_COMMIT() asm volatile("cp.async.commit_group;" ::: "memory")
#define CP_WAIT(n)  asm volatile("cp.async.wait_group %0;" :: "n"(n) : "memory")

// column permutation within each 16-row group of the B tile:
__device__ __forceinline__ int bperm(int q) {
    const int q7 = q & 7;
    return ((q7 >> 1) << 2) + (q & 1) + ((q & 8) ? 2 : 0);
}

// ---------------- prefix phase 1: chunk-local gather + scan (unscaled fp32) ----------------
__global__ void __launch_bounds__(512) p1_kernel(const float* __restrict__ emb,
                                                 const int* __restrict__ x) {
    __shared__ float ebuf[64 * 64];
    const int c = blockIdx.x, b = blockIdx.y;
    const int t = threadIdx.x;
    const int i = t >> 3, q = t & 7;
    const int p0 = c * 64;
    const int idx = x[b * SEQ + p0 + i];
    const float4* src = reinterpret_cast<const float4*>(emb + (size_t)idx * EMB) + q * 2;
    float4 v0 = src[0];
    float4 v1 = src[1];
    *reinterpret_cast<float4*>(ebuf + i * 64 + q * 8)     = v0;
    *reinterpret_cast<float4*>(ebuf + i * 64 + q * 8 + 4) = v1;
    __syncthreads();
    if (t < 64) {
        float run = 0.0f;
        #pragma unroll 8
        for (int p = 0; p < 64; ++p) {
            run += ebuf[p * 64 + t];
            g_S[(size_t)(b * SEQ + p0 + p) * EMB + t] = run;
        }
        g_csum[(b * 32 + c) * EMB + t] = run;
    }
}

// ---------------- prefix phase 2+3 fused: per-block offset sum, apply, fp16-round ----------
__global__ void __launch_bounds__(512) p3_kernel() {
    __shared__ float off[64];
    const int c = blockIdx.x, b = blockIdx.y;
    const int t = threadIdx.x;
    const int i = t >> 3, q = t & 7;

    if (t < 64) {
        float o = 0.0f;
        for (int cc = 0; cc < c; ++cc) o += g_csum[(b * 32 + cc) * EMB + t];
        off[t] = o;
    }
    __syncthreads();

    const int p = c * 64 + i;
    const float inv = __fdividef(1.0f, (float)(p + 1));
    const float* base = g_S + (size_t)(b * SEQ + p) * EMB + q * 8;
    const float* ob   = off + q * 8;
    float4 a0 = *reinterpret_cast<const float4*>(base);
    float4 a1 = *reinterpret_cast<const float4*>(base + 4);
    __half2 h[4];
    h[0] = __floats2half2_rn((a0.x + ob[0]) * inv, (a0.y + ob[1]) * inv);
    h[1] = __floats2half2_rn((a0.z + ob[2]) * inv, (a0.w + ob[3]) * inv);
    h[2] = __floats2half2_rn((a1.x + ob[4]) * inv, (a1.y + ob[5]) * inv);
    h[3] = __floats2half2_rn((a1.z + ob[6]) * inv, (a1.w + ob[7]) * inv);
    *reinterpret_cast<uint4*>(g_A + (size_t)(b * SEQ + p) * EMB + q * 8) =
        *reinterpret_cast<uint4*>(h);
}

// ---------------- GEMM: fp16 mma.sync, in-kernel W convert, triple-buffered A ----------------
// out[m, n] = sum_k A[m,k] * W[n,k] + bias[n]
__global__ void __launch_bounds__(256, 2) gemm_kernel(const float* __restrict__ Wm,
                                                      const float* __restrict__ bias,
                                                      float* __restrict__ out) {
    extern __shared__ char smem[];
    __half* Bs = reinterpret_cast<__half*>(smem + SOFF_B);

    const int tid  = threadIdx.x;
    const int wid  = tid >> 5;
    const int lane = tid & 31;
    const int gid  = lane >> 2;   // 0..7
    const int tig  = lane & 3;    // 0..3
    const int mw   = wid >> 2;    // warp M index 0..1
    const int nw   = wid & 3;     // warp N index 0..3
    const int n0   = blockIdx.x * BN;
    const int yb   = blockIdx.y;  // 0..7

    // rotating A buffers (pointer + smem-u32 pairs, manually rotated)
    const __half* pCur  = reinterpret_cast<__half*>(smem + SOFF_A0);
    const __half* pNext = reinterpret_cast<__half*>(smem + SOFF_A1);
    const __half* pN2   = reinterpret_cast<__half*>(smem + SOFF_A2);
    uint32_t sCur  = smem_u32(pCur);
    uint32_t sNext = smem_u32(pNext);
    uint32_t sN2   = smem_u32(pN2);

    // ---- issue A[0], A[1] prefetches ----
    {
        const __half* gA0 = g_A + (size_t)(yb * BM) * EMB;
        #pragma unroll
        for (int it = 0; it < 4; ++it) {
            const int lin = it * 256 + tid;
            const int r = lin >> 3, f8 = lin & 7;
            CP_ASYNC16(sCur + (uint32_t)(r * HPITCH + f8 * 8) * 2, gA0 + r * EMB + f8 * 8);
        }
        CP_COMMIT();
        const __half* gA1 = g_A + (size_t)((yb + 8) * BM) * EMB;
        #pragma unroll
        for (int it = 0; it < 4; ++it) {
            const int lin = it * 256 + tid;
            const int r = lin >> 3, f8 = lin & 7;
            CP_ASYNC16(sNext + (uint32_t)(r * HPITCH + f8 * 8) * 2, gA1 + r * EMB + f8 * 8);
        }
        CP_COMMIT();
    }

    // ---- stage B tile: LDG fp32 W rows (permuted), convert to fp16, STS ----
    {
        const int r = tid >> 1;            // smem slot row 0..127
        const int part = tid & 1;          // 32-float half of the row
        const int wr = (r & ~15) + bperm(r & 15);
        const float4* src = reinterpret_cast<const float4*>(
            Wm + (size_t)(n0 + wr) * EMB + part * 32);
        __half2 h[16];
        #pragma unroll
        for (int f = 0; f < 8; ++f) {
            float4 v = src[f];
            h[2 * f]     = __floats2half2_rn(v.x, v.y);
            h[2 * f + 1] = __floats2half2_rn(v.z, v.w);
        }
        uint4* dst = reinterpret_cast<uint4*>(Bs + r * HPITCH + part * 32);
        const uint4* hs = reinterpret_cast<const uint4*>(h);
        #pragma unroll
        for (int f = 0; f < 4; ++f) dst[f] = hs[f];
    }

    // bias -> registers (cols contiguous post-perm)
    float4 bias_r[2];
    #pragma unroll
    for (int p = 0; p < 2; ++p)
        bias_r[p] = *reinterpret_cast<const float4*>(bias + n0 + nw * 32 + p * 16 + 4 * tig);

    #pragma unroll 1
    for (int j = 0; j < 8; ++j) {
        if (j < 7) { CP_WAIT(1); } else { CP_WAIT(0); }
        __syncthreads();   // A[j] visible to all; all warps done with iter j-1

        // prefetch A[j+2] into the buffer last read at iter j-1 (safe post-barrier)
        if (j < 6) {
            const __half* gA = g_A + (size_t)((yb + (j + 2) * 8) * BM) * EMB;
            #pragma unroll
            for (int it = 0; it < 4; ++it) {
                const int lin = it * 256 + tid;
                const int r = lin >> 3, f8 = lin & 7;
                CP_ASYNC16(sN2 + (uint32_t)(r * HPITCH + f8 * 8) * 2, gA + r * EMB + f8 * 8);
            }
            CP_COMMIT();
        }

        const __half* Ac = pCur;

        // ---- mainloop: 4 k-steps of 16, warp tile 64x32 ----
        float acc[4][4][4];
        #pragma unroll
        for (int mt = 0; mt < 4; ++mt)
            #pragma unroll
            for (int nt = 0; nt < 4; ++nt)
                #pragma unroll
                for (int rr = 0; rr < 4; ++rr) acc[mt][nt][rr] = 0.0f;

        #pragma unroll
        for (int ks = 0; ks < 4; ++ks) {
            const int k0 = ks * 16;
            uint32_t a[4][4];
            #pragma unroll
            for (int mt = 0; mt < 4; ++mt) {
                const __half* ap = Ac + (mw * 64 + mt * 16 + gid) * HPITCH + k0 + 2 * tig;
                a[mt][0] = *reinterpret_cast<const uint32_t*>(ap);
                a[mt][1] = *reinterpret_cast<const uint32_t*>(ap + 8 * HPITCH);
                a[mt][2] = *reinterpret_cast<const uint32_t*>(ap + 8);
                a[mt][3] = *reinterpret_cast<const uint32_t*>(ap + 8 * HPITCH + 8);
            }
            uint32_t bb[4][2];
            #pragma unroll
            for (int nt = 0; nt < 4; ++nt) {
                const __half* bp = Bs + (nw * 32 + nt * 8 + gid) * HPITCH + k0 + 2 * tig;
                bb[nt][0] = *reinterpret_cast<const uint32_t*>(bp);
                bb[nt][1] = *reinterpret_cast<const uint32_t*>(bp + 8);
            }
            #pragma unroll
            for (int mt = 0; mt < 4; ++mt)
                #pragma unroll
                for (int nt = 0; nt < 4; ++nt)
                    mma_f16(acc[mt][nt], a[mt][0], a[mt][1], a[mt][2], a[mt][3],
                            bb[nt][0], bb[nt][1]);
        }

        // ---- epilogue: direct float4 streaming STG (no trailing barrier) ----
        const int m0 = (yb + j * 8) * BM;
        #pragma unroll
        for (int mt = 0; mt < 4; ++mt) {
            const int row0 = m0 + mw * 64 + mt * 16 + gid;
            float* orow = out + (size_t)row0 * VOCAB + n0 + nw * 32 + 4 * tig;
            #pragma unroll
            for (int p = 0; p < 2; ++p) {
                const float4 bv = bias_r[p];
                float4 v0, v1;
                v0.x = acc[mt][2 * p][0] + bv.x;
                v0.y = acc[mt][2 * p][1] + bv.y;
                v0.z = acc[mt][2 * p + 1][0] + bv.z;
                v0.w = acc[mt][2 * p + 1][1] + bv.w;
                v1.x = acc[mt][2 * p][2] + bv.x;
                v1.y = acc[mt][2 * p][3] + bv.y;
                v1.z = acc[mt][2 * p + 1][2] + bv.z;
                v1.w = acc[mt][2 * p + 1][3] + bv.w;
                __stcs(reinterpret_cast<float4*>(orow + p * 16), v0);
                __stcs(reinterpret_cast<float4*>(orow + (size_t)8 * VOCAB + p * 16), v1);
            }
        }

        // rotate buffers
        const __half* pt = pCur; pCur = pNext; pNext = pN2; pN2 = pt;
        const uint32_t st = sCur; sCur = sNext; sNext = sN2; sN2 = st;
    }
}

// ---------------- launch ----------------
extern "C" void kernel_launch(void* const* d_in, const int* in_sizes, int n_in,
                              void* d_out, int out_size) {
    const float* emb  = (const float*)d_in[0];   // [32000, 64] f32
    const float* Wm   = (const float*)d_in[1];   // [32000, 64] f32
    const float* bias = (const float*)d_in[2];   // [32000] f32
    const int*   x    = (const int*)d_in[3];     // [4, 2048] i32
    float* out = (float*)d_out;                  // [4, 2048, 32000] f32

    p1_kernel<<<dim3(32, BATCH), 512>>>(emb, x);
    p3_kernel<<<dim3(32, BATCH), 512>>>();

    cudaFuncSetAttribute(gemm_kernel, cudaFuncAttributeMaxDynamicSharedMemorySize, SMEM_SZ);
    dim3 grid(VOCAB / BN, 8);   // (250, 8)
    gemm_kernel<<<grid, 256, SMEM_SZ>>>(Wm, bias, out);
}

// round 11
// speedup vs baseline: 1.3040x; 1.0417x over previous
#include <cuda_runtime.h>
#include <cuda_fp16.h>
#include <cstdint>

// ---------------- problem constants ----------------
#define VOCAB 32000
#define EMB   64
#define BATCH 4
#define SEQ   2048
#define MROWS (BATCH * SEQ)   // 8192

// GEMM tiling
#define BM 128
#define BN 128
#define HPITCH 72                        // halves; conflict-free B fragment LDS
#define SMEM_SZ (BN * HPITCH * 2)        // 18432 B (B tile only)

// device scratch
__device__ __half g_Af[MROWS * EMB];      // prefix means, fp16, mma-fragment order
__device__ float  g_S[MROWS * EMB];       // fp32 chunk-local prefix sums
__device__ float  g_csum[BATCH * 32 * EMB];

// ---------------- helpers ----------------
__device__ __forceinline__ uint32_t h2_bits(__half2 h) {
    return *reinterpret_cast<uint32_t*>(&h);
}
__device__ __forceinline__ void mma_f16(float c[4],
                                        uint32_t a0, uint32_t a1, uint32_t a2, uint32_t a3,
                                        uint32_t b0, uint32_t b1) {
    asm volatile(
        "mma.sync.aligned.m16n8k16.row.col.f32.f16.f16.f32 "
        "{%0,%1,%2,%3}, {%4,%5,%6,%7}, {%8,%9}, {%0,%1,%2,%3};"
        : "+f"(c[0]), "+f"(c[1]), "+f"(c[2]), "+f"(c[3])
        : "r"(a0), "r"(a1), "r"(a2), "r"(a3), "r"(b0), "r"(b1));
}

// column permutation within each 16-row group of the B tile (epilogue contiguity)
__device__ __forceinline__ int bperm(int q) {
    const int q7 = q & 7;
    return ((q7 >> 1) << 2) + (q & 1) + ((q & 8) ? 2 : 0);
}

// ---------------- prefix phase 1: chunk-local gather + scan (unscaled fp32) ----------------
__global__ void __launch_bounds__(512) p1_kernel(const float* __restrict__ emb,
                                                 const int* __restrict__ x) {
    __shared__ float ebuf[64 * 64];
    const int c = blockIdx.x, b = blockIdx.y;
    const int t = threadIdx.x;
    const int i = t >> 3, q = t & 7;
    const int p0 = c * 64;
    const int idx = x[b * SEQ + p0 + i];
    const float4* src = reinterpret_cast<const float4*>(emb + (size_t)idx * EMB) + q * 2;
    float4 v0 = src[0];
    float4 v1 = src[1];
    *reinterpret_cast<float4*>(ebuf + i * 64 + q * 8)     = v0;
    *reinterpret_cast<float4*>(ebuf + i * 64 + q * 8 + 4) = v1;
    __syncthreads();
    if (t < 64) {
        float run = 0.0f;
        #pragma unroll 8
        for (int p = 0; p < 64; ++p) {
            run += ebuf[p * 64 + t];
            g_S[(size_t)(b * SEQ + p0 + p) * EMB + t] = run;
        }
        g_csum[(b * 32 + c) * EMB + t] = run;
    }
}

// ---------------- prefix phase 2+3 fused: offsets, scale, fp16, FRAGMENT-ORDER store ----
// Fragment layout: for each 16x16 A tile T (row-tile) and ks (k-tile of 16),
// 32 lanes x 4 uint32: lane = gid*4 + tig holds
//   slot0 = A[gid][2tig:2tig+1]    slot1 = A[gid+8][2tig:2tig+1]
//   slot2 = A[gid][8+2tig:...]     slot3 = A[gid+8][8+2tig:...]
// address (uint32 units) = ((T*4 + ks)*32 + lane)*4 + slot
__global__ void __launch_bounds__(512) p3_kernel() {
    __shared__ float off[64];
    const int c = blockIdx.x, b = blockIdx.y;
    const int t = threadIdx.x;
    const int i = t >> 3, q = t & 7;

    if (t < 64) {
        float o = 0.0f;
        for (int cc = 0; cc < c; ++cc) o += g_csum[(b * 32 + cc) * EMB + t];
        off[t] = o;
    }
    __syncthreads();

    const int p = c * 64 + i;
    const float inv = __fdividef(1.0f, (float)(p + 1));
    const float* base = g_S + (size_t)(b * SEQ + p) * EMB + q * 8;
    const float* ob   = off + q * 8;
    float4 a0 = *reinterpret_cast<const float4*>(base);
    float4 a1 = *reinterpret_cast<const float4*>(base + 4);
    uint32_t h[4];
    h[0] = h2_bits(__floats2half2_rn((a0.x + ob[0]) * inv, (a0.y + ob[1]) * inv));
    h[1] = h2_bits(__floats2half2_rn((a0.z + ob[2]) * inv, (a0.w + ob[3]) * inv));
    h[2] = h2_bits(__floats2half2_rn((a1.x + ob[4]) * inv, (a1.y + ob[5]) * inv));
    h[3] = h2_bits(__floats2half2_rn((a1.z + ob[6]) * inv, (a1.w + ob[7]) * inv));

    const int m    = b * SEQ + p;       // global row
    const int Tm   = m >> 4;            // 16-row tile
    const int r    = m & 15;
    const int gid8 = r & 7;
    const int hi   = r >> 3;            // 0 -> a0/a2 rows, 1 -> a1/a3 rows
    // q = feature octet 0..7; h[d] covers k = q*8 + 2d .. +1
    // k-tile ks = (q*8+2d)>>4 = q>>1 ; within-tile half hh = (q&1)
    const int ks   = q >> 1;
    const int hh   = q & 1;             // 0 -> slots {0,1}, 1 -> slots {2,3}
    const int slot = hh * 2 + hi;

    uint32_t* dst = reinterpret_cast<uint32_t*>(g_Af) +
                    ((size_t)(Tm * 4 + ks) * 32 + gid8 * 4) * 4 + slot;
    // d=0..3 pairs k=2d within this 8-wide half -> lane tig = d
    #pragma unroll
    for (int d = 0; d < 4; ++d) dst[d * 4] = h[d];
}

// ---------------- GEMM: fp16 mma.sync, fragment-order A via LDG.128, barrier-free j-loop --
// out[m, n] = sum_k A[m,k] * W[n,k] + bias[n]
__global__ void __launch_bounds__(256, 2) gemm_kernel(const float* __restrict__ Wm,
                                                      const float* __restrict__ bias,
                                                      float* __restrict__ out) {
    extern __shared__ char smem[];
    __half* Bs = reinterpret_cast<__half*>(smem);

    const int tid  = threadIdx.x;
    const int wid  = tid >> 5;
    const int lane = tid & 31;
    const int gid  = lane >> 2;   // 0..7
    const int tig  = lane & 3;    // 0..3
    const int mw   = wid >> 2;    // warp M index 0..1
    const int nw   = wid & 3;     // warp N index 0..3
    const int n0   = blockIdx.x * BN;
    const int yb   = blockIdx.y;  // 0..7

    // ---- stage B tile: LDG fp32 W rows (permuted), convert to fp16, STS ----
    {
        const int r = tid >> 1;            // smem slot row 0..127
        const int part = tid & 1;          // 32-float half of the row
        const int wr = (r & ~15) + bperm(r & 15);
        const float4* src = reinterpret_cast<const float4*>(
            Wm + (size_t)(n0 + wr) * EMB + part * 32);
        __half2 h[16];
        #pragma unroll
        for (int f = 0; f < 8; ++f) {
            float4 v = src[f];
            h[2 * f]     = __floats2half2_rn(v.x, v.y);
            h[2 * f + 1] = __floats2half2_rn(v.z, v.w);
        }
        uint4* dst = reinterpret_cast<uint4*>(Bs + r * HPITCH + part * 32);
        const uint4* hs = reinterpret_cast<const uint4*>(h);
        #pragma unroll
        for (int f = 0; f < 4; ++f) dst[f] = hs[f];
    }

    // bias -> registers (cols contiguous post-perm)
    float4 bias_r[2];
    #pragma unroll
    for (int p = 0; p < 2; ++p)
        bias_r[p] = *reinterpret_cast<const float4*>(bias + n0 + nw * 32 + p * 16 + 4 * tig);

    __syncthreads();   // only barrier in the kernel; Bs read-only afterwards

    const uint4* __restrict__ Af = reinterpret_cast<const uint4*>(g_Af);

    #pragma unroll 1
    for (int j = 0; j < 8; ++j) {
        // warp's 4 M-tiles this iteration (16 rows each)
        const int Tbase = ((yb + j * 8) * 8 + mw * 4);

        float acc[4][4][4];
        #pragma unroll
        for (int mt = 0; mt < 4; ++mt)
            #pragma unroll
            for (int nt = 0; nt < 4; ++nt)
                #pragma unroll
                for (int rr = 0; rr < 4; ++rr) acc[mt][nt][rr] = 0.0f;

        #pragma unroll
        for (int ks = 0; ks < 4; ++ks) {
            const int k0 = ks * 16;
            // A fragments: one coalesced LDG.128 per mt
            uint4 av[4];
            #pragma unroll
            for (int mt = 0; mt < 4; ++mt)
                av[mt] = Af[(size_t)((Tbase + mt) * 4 + ks) * 32 + lane];
            // B fragments from smem
            uint32_t bb[4][2];
            #pragma unroll
            for (int nt = 0; nt < 4; ++nt) {
                const __half* bp = Bs + (nw * 32 + nt * 8 + gid) * HPITCH + k0 + 2 * tig;
                bb[nt][0] = *reinterpret_cast<const uint32_t*>(bp);
                bb[nt][1] = *reinterpret_cast<const uint32_t*>(bp + 8);
            }
            #pragma unroll
            for (int mt = 0; mt < 4; ++mt)
                #pragma unroll
                for (int nt = 0; nt < 4; ++nt)
                    mma_f16(acc[mt][nt], av[mt].x, av[mt].y, av[mt].z, av[mt].w,
                            bb[nt][0], bb[nt][1]);
        }

        // ---- epilogue: direct float4 streaming STG (cols contiguous via B perm) ----
        const int m0 = (yb + j * 8) * BM;
        #pragma unroll
        for (int mt = 0; mt < 4; ++mt) {
            const int row0 = m0 + mw * 64 + mt * 16 + gid;
            float* orow = out + (size_t)row0 * VOCAB + n0 + nw * 32 + 4 * tig;
            #pragma unroll
            for (int p = 0; p < 2; ++p) {
                const float4 bv = bias_r[p];
                float4 v0, v1;
                v0.x = acc[mt][2 * p][0] + bv.x;
                v0.y = acc[mt][2 * p][1] + bv.y;
                v0.z = acc[mt][2 * p + 1][0] + bv.z;
                v0.w = acc[mt][2 * p + 1][1] + bv.w;
                v1.x = acc[mt][2 * p][2] + bv.x;
                v1.y = acc[mt][2 * p][3] + bv.y;
                v1.z = acc[mt][2 * p + 1][2] + bv.z;
                v1.w = acc[mt][2 * p + 1][3] + bv.w;
                __stcs(reinterpret_cast<float4*>(orow + p * 16), v0);
                __stcs(reinterpret_cast<float4*>(orow + (size_t)8 * VOCAB + p * 16), v1);
            }
        }
    }
}

// ---------------- launch ----------------
extern "C" void kernel_launch(void* const* d_in, const int* in_sizes, int n_in,
                              void* d_out, int out_size) {
    const float* emb  = (const float*)d_in[0];   // [32000, 64] f32
    const float* Wm   = (const float*)d_in[1];   // [32000, 64] f32
    const float* bias = (const float*)d_in[2];   // [32000] f32
    const int*   x    = (const int*)d_in[3];     // [4, 2048] i32
    float* out = (float*)d_out;                  // [4, 2048, 32000] f32

    p1_kernel<<<dim3(32, BATCH), 512>>>(emb, x);
    p3_kernel<<<dim3(32, BATCH), 512>>>();

    cudaFuncSetAttribute(gemm_kernel, cudaFuncAttributeMaxDynamicSharedMemorySize, SMEM_SZ);
    dim3 grid(VOCAB / BN, 8);   // (250, 8)
    gemm_kernel<<<grid, 256, SMEM_SZ>>>(Wm, bias, out);
}

// round 12
// speedup vs baseline: 1.3686x; 1.0495x over previous
#include <cuda_runtime.h>
#include <cuda_fp16.h>
#include <cstdint>

// ---------------- problem constants ----------------
#define VOCAB 32000
#define EMB   64
#define BATCH 4
#define SEQ   2048
#define MROWS (BATCH * SEQ)   // 8192

// GEMM tiling
#define BM 128
#define BN 128

// device scratch
__device__ __half g_Af[MROWS * EMB];      // prefix means, fp16, mma-fragment order
__device__ float  g_S[MROWS * EMB];       // fp32 chunk-local prefix sums
__device__ float  g_csum[BATCH * 32 * EMB];

// ---------------- helpers ----------------
__device__ __forceinline__ uint32_t h2_bits(__half2 h) {
    return *reinterpret_cast<uint32_t*>(&h);
}
__device__ __forceinline__ void mma_f16(float c[4],
                                        uint32_t a0, uint32_t a1, uint32_t a2, uint32_t a3,
                                        uint32_t b0, uint32_t b1) {
    asm volatile(
        "mma.sync.aligned.m16n8k16.row.col.f32.f16.f16.f32 "
        "{%0,%1,%2,%3}, {%4,%5,%6,%7}, {%8,%9}, {%0,%1,%2,%3};"
        : "+f"(c[0]), "+f"(c[1]), "+f"(c[2]), "+f"(c[3])
        : "r"(a0), "r"(a1), "r"(a2), "r"(a3), "r"(b0), "r"(b1));
}

// column permutation within each 16-row group of the B tile (epilogue contiguity)
__device__ __forceinline__ int bperm(int q) {
    const int q7 = q & 7;
    return ((q7 >> 1) << 2) + (q & 1) + ((q & 8) ? 2 : 0);
}

// ---------------- prefix phase 1: chunk-local gather + scan (unscaled fp32) ----------------
__global__ void __launch_bounds__(512) p1_kernel(const float* __restrict__ emb,
                                                 const int* __restrict__ x) {
    __shared__ float ebuf[64 * 64];
    const int c = blockIdx.x, b = blockIdx.y;
    const int t = threadIdx.x;
    const int i = t >> 3, q = t & 7;
    const int p0 = c * 64;
    const int idx = x[b * SEQ + p0 + i];
    const float4* src = reinterpret_cast<const float4*>(emb + (size_t)idx * EMB) + q * 2;
    float4 v0 = src[0];
    float4 v1 = src[1];
    *reinterpret_cast<float4*>(ebuf + i * 64 + q * 8)     = v0;
    *reinterpret_cast<float4*>(ebuf + i * 64 + q * 8 + 4) = v1;
    __syncthreads();
    if (t < 64) {
        float run = 0.0f;
        #pragma unroll 8
        for (int p = 0; p < 64; ++p) {
            run += ebuf[p * 64 + t];
            g_S[(size_t)(b * SEQ + p0 + p) * EMB + t] = run;
        }
        g_csum[(b * 32 + c) * EMB + t] = run;
    }
}

// ---------------- prefix phase 2+3 fused: offsets, scale, fp16, FRAGMENT-ORDER store ----
__global__ void __launch_bounds__(512) p3_kernel() {
    __shared__ float off[64];
    const int c = blockIdx.x, b = blockIdx.y;
    const int t = threadIdx.x;
    const int i = t >> 3, q = t & 7;

    if (t < 64) {
        float o = 0.0f;
        for (int cc = 0; cc < c; ++cc) o += g_csum[(b * 32 + cc) * EMB + t];
        off[t] = o;
    }
    __syncthreads();

    const int p = c * 64 + i;
    const float inv = __fdividef(1.0f, (float)(p + 1));
    const float* base = g_S + (size_t)(b * SEQ + p) * EMB + q * 8;
    const float* ob   = off + q * 8;
    float4 a0 = *reinterpret_cast<const float4*>(base);
    float4 a1 = *reinterpret_cast<const float4*>(base + 4);
    uint32_t h[4];
    h[0] = h2_bits(__floats2half2_rn((a0.x + ob[0]) * inv, (a0.y + ob[1]) * inv));
    h[1] = h2_bits(__floats2half2_rn((a0.z + ob[2]) * inv, (a0.w + ob[3]) * inv));
    h[2] = h2_bits(__floats2half2_rn((a1.x + ob[4]) * inv, (a1.y + ob[5]) * inv));
    h[3] = h2_bits(__floats2half2_rn((a1.z + ob[6]) * inv, (a1.w + ob[7]) * inv));

    const int m    = b * SEQ + p;
    const int Tm   = m >> 4;
    const int r    = m & 15;
    const int gid8 = r & 7;
    const int hi   = r >> 3;
    const int ks   = q >> 1;
    const int hh   = q & 1;
    const int slot = hh * 2 + hi;

    uint32_t* dst = reinterpret_cast<uint32_t*>(g_Af) +
                    ((size_t)(Tm * 4 + ks) * 32 + gid8 * 4) * 4 + slot;
    #pragma unroll
    for (int d = 0; d < 4; ++d) dst[d * 4] = h[d];
}

// ---------------- GEMM: fp16 mma.sync, register-resident B, zero smem, zero barriers ------
// out[m, n] = sum_k A[m,k] * W[n,k] + bias[n]
__global__ void __launch_bounds__(256, 2) gemm_kernel(const float* __restrict__ Wm,
                                                      const float* __restrict__ bias,
                                                      float* __restrict__ out) {
    const int tid  = threadIdx.x;
    const int wid  = tid >> 5;
    const int lane = tid & 31;
    const int gid  = lane >> 2;   // 0..7
    const int tig  = lane & 3;    // 0..3
    const int mw   = wid >> 2;    // warp M index 0..1
    const int nw   = wid & 3;     // warp N index 0..3
    const int n0   = blockIdx.x * BN;
    const int yb   = blockIdx.y;  // 0..7

    // ---- B fragments -> registers (constant across the whole j-loop) ----
    uint32_t bb[4][4][2];   // [nt][ks][half]
    #pragma unroll
    for (int nt = 0; nt < 4; ++nt) {
        const int r  = nw * 32 + nt * 8 + gid;
        const int wr = (r & ~15) + bperm(r & 15);
        const float* wrow = Wm + (size_t)(n0 + wr) * EMB;
        #pragma unroll
        for (int ks = 0; ks < 4; ++ks) {
            float2 lo = *reinterpret_cast<const float2*>(wrow + ks * 16 + 2 * tig);
            float2 hi = *reinterpret_cast<const float2*>(wrow + ks * 16 + 8 + 2 * tig);
            bb[nt][ks][0] = h2_bits(__floats2half2_rn(lo.x, lo.y));
            bb[nt][ks][1] = h2_bits(__floats2half2_rn(hi.x, hi.y));
        }
    }

    const uint4* __restrict__ Af = reinterpret_cast<const uint4*>(g_Af);
    const float4* __restrict__ bias4 =
        reinterpret_cast<const float4*>(bias + n0 + nw * 32 + 4 * tig);

    #pragma unroll 1
    for (int j = 0; j < 8; ++j) {
        const int Tbase = ((yb + j * 8) * 8 + mw * 4);

        float acc[4][4][4];
        #pragma unroll
        for (int mt = 0; mt < 4; ++mt)
            #pragma unroll
            for (int nt = 0; nt < 4; ++nt)
                #pragma unroll
                for (int rr = 0; rr < 4; ++rr) acc[mt][nt][rr] = 0.0f;

        #pragma unroll
        for (int ks = 0; ks < 4; ++ks) {
            uint4 av[4];
            #pragma unroll
            for (int mt = 0; mt < 4; ++mt)
                av[mt] = Af[(size_t)((Tbase + mt) * 4 + ks) * 32 + lane];
            #pragma unroll
            for (int mt = 0; mt < 4; ++mt)
                #pragma unroll
                for (int nt = 0; nt < 4; ++nt)
                    mma_f16(acc[mt][nt], av[mt].x, av[mt].y, av[mt].z, av[mt].w,
                            bb[nt][ks][0], bb[nt][ks][1]);
        }

        // ---- epilogue: direct float4 streaming STG (cols contiguous via B perm) ----
        const int m0 = (yb + j * 8) * BM;
        #pragma unroll
        for (int mt = 0; mt < 4; ++mt) {
            const int row0 = m0 + mw * 64 + mt * 16 + gid;
            float* orow = out + (size_t)row0 * VOCAB + n0 + nw * 32 + 4 * tig;
            #pragma unroll
            for (int p = 0; p < 2; ++p) {
                const float4 bv = __ldg(bias4 + p * 4);   // 16 cols -> 4 float4s apart
                float4 v0, v1;
                v0.x = acc[mt][2 * p][0] + bv.x;
                v0.y = acc[mt][2 * p][1] + bv.y;
                v0.z = acc[mt][2 * p + 1][0] + bv.z;
                v0.w = acc[mt][2 * p + 1][1] + bv.w;
                v1.x = acc[mt][2 * p][2] + bv.x;
                v1.y = acc[mt][2 * p][3] + bv.y;
                v1.z = acc[mt][2 * p + 1][2] + bv.z;
                v1.w = acc[mt][2 * p + 1][3] + bv.w;
                __stcs(reinterpret_cast<float4*>(orow + p * 16), v0);
                __stcs(reinterpret_cast<float4*>(orow + (size_t)8 * VOCAB + p * 16), v1);
            }
        }
    }
}

// ---------------- launch ----------------
extern "C" void kernel_launch(void* const* d_in, const int* in_sizes, int n_in,
                              void* d_out, int out_size) {
    const float* emb  = (const float*)d_in[0];   // [32000, 64] f32
    const float* Wm   = (const float*)d_in[1];   // [32000, 64] f32
    const float* bias = (const float*)d_in[2];   // [32000] f32
    const int*   x    = (const int*)d_in[3];     // [4, 2048] i32
    float* out = (float*)d_out;                  // [4, 2048, 32000] f32

    p1_kernel<<<dim3(32, BATCH), 512>>>(emb, x);
    p3_kernel<<<dim3(32, BATCH), 512>>>();

    dim3 grid(VOCAB / BN, 8);   // (250, 8)
    gemm_kernel<<<grid, 256>>>(Wm, bias, out);
}

// round 13
// speedup vs baseline: 1.3763x; 1.0056x over previous
#include <cuda_runtime.h>
#include <cuda_fp16.h>
#include <cstdint>

// ---------------- problem constants ----------------
#define VOCAB 32000
#define EMB   64
#define BATCH 4
#define SEQ   2048
#define MROWS (BATCH * SEQ)   // 8192

// GEMM tiling
#define BM 128
#define BN 128

// device scratch
__device__ __half g_Af[MROWS * EMB];      // prefix means, fp16, mma-fragment order
__device__ float  g_S[MROWS * EMB];       // fp32 chunk-local prefix sums
__device__ float  g_csum[BATCH * 32 * EMB];

// ---------------- helpers ----------------
__device__ __forceinline__ uint32_t h2_bits(__half2 h) {
    return *reinterpret_cast<uint32_t*>(&h);
}
__device__ __forceinline__ void mma_f16(float c[4],
                                        uint32_t a0, uint32_t a1, uint32_t a2, uint32_t a3,
                                        uint32_t b0, uint32_t b1) {
    asm volatile(
        "mma.sync.aligned.m16n8k16.row.col.f32.f16.f16.f32 "
        "{%0,%1,%2,%3}, {%4,%5,%6,%7}, {%8,%9}, {%0,%1,%2,%3};"
        : "+f"(c[0]), "+f"(c[1]), "+f"(c[2]), "+f"(c[3])
        : "r"(a0), "r"(a1), "r"(a2), "r"(a3), "r"(b0), "r"(b1));
}

// column permutation within each 16-row group of the B tile (epilogue contiguity)
__device__ __forceinline__ int bperm(int q) {
    const int q7 = q & 7;
    return ((q7 >> 1) << 2) + (q & 1) + ((q & 8) ? 2 : 0);
}

// ---------------- prefix phase 1: chunk-local gather + scan (unscaled fp32) ----------------
__global__ void __launch_bounds__(512) p1_kernel(const float* __restrict__ emb,
                                                 const int* __restrict__ x) {
    __shared__ float ebuf[64 * 64];
    const int c = blockIdx.x, b = blockIdx.y;
    const int t = threadIdx.x;
    const int i = t >> 3, q = t & 7;
    const int p0 = c * 64;
    const int idx = x[b * SEQ + p0 + i];
    const float4* src = reinterpret_cast<const float4*>(emb + (size_t)idx * EMB) + q * 2;
    float4 v0 = src[0];
    float4 v1 = src[1];
    *reinterpret_cast<float4*>(ebuf + i * 64 + q * 8)     = v0;
    *reinterpret_cast<float4*>(ebuf + i * 64 + q * 8 + 4) = v1;
    __syncthreads();
    if (t < 64) {
        float run = 0.0f;
        #pragma unroll 8
        for (int p = 0; p < 64; ++p) {
            run += ebuf[p * 64 + t];
            g_S[(size_t)(b * SEQ + p0 + p) * EMB + t] = run;
        }
        g_csum[(b * 32 + c) * EMB + t] = run;
    }
}

// ---------------- prefix phase 2+3 fused: offsets, scale, fp16, FRAGMENT-ORDER store ----
__global__ void __launch_bounds__(512) p3_kernel() {
    __shared__ float off[64];
    const int c = blockIdx.x, b = blockIdx.y;
    const int t = threadIdx.x;
    const int i = t >> 3, q = t & 7;

    if (t < 64) {
        float o = 0.0f;
        for (int cc = 0; cc < c; ++cc) o += g_csum[(b * 32 + cc) * EMB + t];
        off[t] = o;
    }
    __syncthreads();

    const int p = c * 64 + i;
    const float inv = __fdividef(1.0f, (float)(p + 1));
    const float* base = g_S + (size_t)(b * SEQ + p) * EMB + q * 8;
    const float* ob   = off + q * 8;
    float4 a0 = *reinterpret_cast<const float4*>(base);
    float4 a1 = *reinterpret_cast<const float4*>(base + 4);
    uint32_t h[4];
    h[0] = h2_bits(__floats2half2_rn((a0.x + ob[0]) * inv, (a0.y + ob[1]) * inv));
    h[1] = h2_bits(__floats2half2_rn((a0.z + ob[2]) * inv, (a0.w + ob[3]) * inv));
    h[2] = h2_bits(__floats2half2_rn((a1.x + ob[4]) * inv, (a1.y + ob[5]) * inv));
    h[3] = h2_bits(__floats2half2_rn((a1.z + ob[6]) * inv, (a1.w + ob[7]) * inv));

    const int m    = b * SEQ + p;
    const int Tm   = m >> 4;
    const int r    = m & 15;
    const int gid8 = r & 7;
    const int hi   = r >> 3;
    const int ks   = q >> 1;
    const int hh   = q & 1;
    const int slot = hh * 2 + hi;

    uint32_t* dst = reinterpret_cast<uint32_t*>(g_Af) +
                    ((size_t)(Tm * 4 + ks) * 32 + gid8 * 4) * 4 + slot;
    #pragma unroll
    for (int d = 0; d < 4; ++d) dst[d * 4] = h[d];
}

// ---------------- GEMM: fp16 mma.sync, register B, bias-seeded accumulators --------------
// out[m, n] = sum_k A[m,k] * W[n,k] + bias[n]
__global__ void __launch_bounds__(256, 2) gemm_kernel(const float* __restrict__ Wm,
                                                      const float* __restrict__ bias,
                                                      float* __restrict__ out) {
    const int tid  = threadIdx.x;
    const int wid  = tid >> 5;
    const int lane = tid & 31;
    const int gid  = lane >> 2;   // 0..7
    const int tig  = lane & 3;    // 0..3
    const int mw   = wid >> 2;    // warp M index 0..1
    const int nw   = wid & 3;     // warp N index 0..3
    const int n0   = blockIdx.x * BN;
    const int yb   = blockIdx.y;  // 0..7

    // ---- B fragments -> registers (constant across the whole j-loop) ----
    uint32_t bb[4][4][2];   // [nt][ks][half]
    #pragma unroll
    for (int nt = 0; nt < 4; ++nt) {
        const int r  = nw * 32 + nt * 8 + gid;
        const int wr = (r & ~15) + bperm(r & 15);
        const float* wrow = Wm + (size_t)(n0 + wr) * EMB;
        #pragma unroll
        for (int ks = 0; ks < 4; ++ks) {
            float2 lo = *reinterpret_cast<const float2*>(wrow + ks * 16 + 2 * tig);
            float2 hi = *reinterpret_cast<const float2*>(wrow + ks * 16 + 8 + 2 * tig);
            bb[nt][ks][0] = h2_bits(__floats2half2_rn(lo.x, lo.y));
            bb[nt][ks][1] = h2_bits(__floats2half2_rn(hi.x, hi.y));
        }
    }

    // bias -> persistent registers (post-perm contiguous cols)
    float4 bias_r[2];
    #pragma unroll
    for (int p = 0; p < 2; ++p)
        bias_r[p] = *reinterpret_cast<const float4*>(bias + n0 + nw * 32 + p * 16 + 4 * tig);

    const uint4* __restrict__ Af = reinterpret_cast<const uint4*>(g_Af);

    #pragma unroll 1
    for (int j = 0; j < 8; ++j) {
        const int Tbase = ((yb + j * 8) * 8 + mw * 4);

        // accumulators seeded with bias: d = A*B + bias after the mma chain
        float acc[4][4][4];
        #pragma unroll
        for (int mt = 0; mt < 4; ++mt) {
            #pragma unroll
            for (int p = 0; p < 2; ++p) {
                const float4 bv = bias_r[p];
                acc[mt][2 * p][0] = bv.x;  acc[mt][2 * p][1] = bv.y;
                acc[mt][2 * p][2] = bv.x;  acc[mt][2 * p][3] = bv.y;
                acc[mt][2 * p + 1][0] = bv.z;  acc[mt][2 * p + 1][1] = bv.w;
                acc[mt][2 * p + 1][2] = bv.z;  acc[mt][2 * p + 1][3] = bv.w;
            }
        }

        #pragma unroll
        for (int ks = 0; ks < 4; ++ks) {
            uint4 av[4];
            #pragma unroll
            for (int mt = 0; mt < 4; ++mt)
                av[mt] = Af[(size_t)((Tbase + mt) * 4 + ks) * 32 + lane];
            #pragma unroll
            for (int mt = 0; mt < 4; ++mt)
                #pragma unroll
                for (int nt = 0; nt < 4; ++nt)
                    mma_f16(acc[mt][nt], av[mt].x, av[mt].y, av[mt].z, av[mt].w,
                            bb[nt][ks][0], bb[nt][ks][1]);
        }

        // ---- epilogue: pure packing + streaming STG (bias already inside) ----
        const int m0 = (yb + j * 8) * BM;
        #pragma unroll
        for (int mt = 0; mt < 4; ++mt) {
            const int row0 = m0 + mw * 64 + mt * 16 + gid;
            float* orow = out + (size_t)row0 * VOCAB + n0 + nw * 32 + 4 * tig;
            #pragma unroll
            for (int p = 0; p < 2; ++p) {
                float4 v0, v1;
                v0.x = acc[mt][2 * p][0];
                v0.y = acc[mt][2 * p][1];
                v0.z = acc[mt][2 * p + 1][0];
                v0.w = acc[mt][2 * p + 1][1];
                v1.x = acc[mt][2 * p][2];
                v1.y = acc[mt][2 * p][3];
                v1.z = acc[mt][2 * p + 1][2];
                v1.w = acc[mt][2 * p + 1][3];
                __stcs(reinterpret_cast<float4*>(orow + p * 16), v0);
                __stcs(reinterpret_cast<float4*>(orow + (size_t)8 * VOCAB + p * 16), v1);
            }
        }
    }
}

// ---------------- launch ----------------
extern "C" void kernel_launch(void* const* d_in, const int* in_sizes, int n_in,
                              void* d_out, int out_size) {
    const float* emb  = (const float*)d_in[0];   // [32000, 64] f32
    const float* Wm   = (const float*)d_in[1];   // [32000, 64] f32
    const float* bias = (const float*)d_in[2];   // [32000] f32
    const int*   x    = (const int*)d_in[3];     // [4, 2048] i32
    float* out = (float*)d_out;                  // [4, 2048, 32000] f32

    p1_kernel<<<dim3(32, BATCH), 512>>>(emb, x);
    p3_kernel<<<dim3(32, BATCH), 512>>>();

    dim3 grid(VOCAB / BN, 8);   // (250, 8)
    gemm_kernel<<<grid, 256>>>(Wm, bias, out);
}